// round 3
// baseline (speedup 1.0000x reference)
#include <cuda_runtime.h>
#include <cuda_bf16.h>

// Problem constants
#define BB 8
#define CC 512
#define OO 512
#define HH 64
#define WW 64
#define MOD_SCALE_F 0.04419417382415922f   // 1/sqrt(512)

#define CCHUNK 8

// Scratch (device globals; no allocation in kernel_launch)
__device__ float d_s[BB * CC];           // modulation s[b,c]
__device__ float d_W2[OO * CC];          // sum_k base[o,c,k]^2
__device__ float d_g[BB * OO];           // output scale g[b,o]
__device__ float d_xs[BB * CC * HH * WW];// modulated input x*s

// ---------------------------------------------------------------------------
// Stage 1: s[b,c] = MOD_SCALE * (w[b,:] . mod_weight[c,:]) + mod_bias[c] + 1
// one warp per (b,c)
// ---------------------------------------------------------------------------
__global__ void s_kernel(const float* __restrict__ w,
                         const float* __restrict__ mw,
                         const float* __restrict__ mb) {
    int gid = blockIdx.x * blockDim.x + threadIdx.x;
    int wid = gid >> 5;
    int lane = gid & 31;
    if (wid >= BB * CC) return;
    int b = wid >> 9;
    int c = wid & 511;
    const float* wr = w + b * 512;
    const float* mr = mw + c * 512;
    float acc = 0.f;
    #pragma unroll 4
    for (int d = lane; d < 512; d += 32) acc = fmaf(wr[d], mr[d], acc);
    #pragma unroll
    for (int off = 16; off; off >>= 1) acc += __shfl_xor_sync(0xffffffffu, acc, off);
    if (lane == 0) d_s[wid] = acc * MOD_SCALE_F + mb[c] + 1.0f;
}

// ---------------------------------------------------------------------------
// Stage 2: W2[o,c] = sum_k base[o,c,k]^2
// ---------------------------------------------------------------------------
__global__ void w2_kernel(const float* __restrict__ base) {
    int i = blockIdx.x * blockDim.x + threadIdx.x;
    if (i >= OO * CC) return;
    const float* p = base + (size_t)i * 9;
    float a = 0.f;
    #pragma unroll
    for (int k = 0; k < 9; k++) { float v = p[k]; a = fmaf(v, v, a); }
    d_W2[i] = a;
}

// ---------------------------------------------------------------------------
// Stage 3: g[b,o] = rsqrt( sum_c s[b,c]^2 * W2[o,c] )   (CONV_SCALE cancels)
// one warp per (b,o)
// ---------------------------------------------------------------------------
__global__ void g_kernel() {
    int gid = blockIdx.x * blockDim.x + threadIdx.x;
    int wid = gid >> 5;
    int lane = gid & 31;
    if (wid >= BB * OO) return;
    int b = wid >> 9;
    int o = wid & 511;
    const float* sr = d_s + b * 512;
    const float* w2 = d_W2 + o * 512;
    float acc = 0.f;
    #pragma unroll 4
    for (int c = lane; c < 512; c += 32) {
        float sv = sr[c];
        acc = fmaf(sv * sv, w2[c], acc);
    }
    #pragma unroll
    for (int off = 16; off; off >>= 1) acc += __shfl_xor_sync(0xffffffffu, acc, off);
    if (lane == 0) d_g[wid] = rsqrtf(acc);
}

// ---------------------------------------------------------------------------
// Stage 4: xs[b,c,:,:] = x[b,c,:,:] * s[b,c]   (float4 vectorized)
// ---------------------------------------------------------------------------
__global__ void xs_kernel(const float* __restrict__ x) {
    int i = blockIdx.x * blockDim.x + threadIdx.x;
    if (i >= (BB * CC * HH * WW) / 4) return;
    float sc = d_s[i >> 10];  // 4096/4 = 1024 float4 per (b,c) plane
    float4 v = ((const float4*)x)[i];
    v.x *= sc; v.y *= sc; v.z *= sc; v.w *= sc;
    ((float4*)d_xs)[i] = v;
}

// ---------------------------------------------------------------------------
// Stage 5: main conv. y[b,o,h,w] = g[b,o] * conv3x3(xs[b], base)[o,h,w]
// CTA: 64 O-channels x 16x16 spatial tile, one b.
// Thread: 4 O x 4x4 pixels, 6x6 input patch cached in registers per channel.
// ---------------------------------------------------------------------------
__global__ __launch_bounds__(256, 2) void conv_kernel(
    const float* __restrict__ base, float* __restrict__ out) {
    __shared__ float sx[CCHUNK][18][20];   // padded cols for float4 alignment
    __shared__ float sw[CCHUNK][9][65];    // padded for conflict-free STS

    const int b    = blockIdx.z;
    const int og   = blockIdx.y;             // o base = og*64
    const int tile = blockIdx.x;             // 0..15
    const int th0  = (tile >> 2) << 4;
    const int tw0  = (tile & 3) << 4;
    const int tid  = threadIdx.x;
    const int tp   = tid & 15;               // pixel thread 0..15
    const int to   = tid >> 4;               // o thread 0..15
    const int pr   = (tp >> 2) << 2;         // pixel-row base 0,4,8,12
    const int pc   = (tp & 3) << 2;          // pixel-col base 0,4,8,12

    float acc[4][4][4];
    #pragma unroll
    for (int j = 0; j < 4; j++)
        #pragma unroll
        for (int r = 0; r < 4; r++)
            #pragma unroll
            for (int q = 0; q < 4; q++) acc[j][r][q] = 0.f;

    const float* xb = d_xs + (size_t)b * (CC * HH * WW);

    for (int c0 = 0; c0 < CC; c0 += CCHUNK) {
        __syncthreads();
        // load x tile (CCHUNK x 18 x 18, zero-padded halo)
        for (int idx = tid; idx < CCHUNK * 18 * 18; idx += 256) {
            int ch  = idx / 324;
            int rem = idx - ch * 324;
            int r   = rem / 18;
            int cc  = rem - r * 18;
            int gh  = th0 + r - 1;
            int gw  = tw0 + cc - 1;
            float v = 0.f;
            if (gh >= 0 && gh < HH && gw >= 0 && gw < WW)
                v = xb[((c0 + ch) * HH + gh) * WW + gw];
            sx[ch][r][cc] = v;
        }
        // load weights: 64 o x CCHUNK x 9  (base layout [o][c][k])
        for (int idx = tid; idx < 64 * CCHUNK * 9; idx += 256) {
            int oo  = idx / (CCHUNK * 9);
            int rem = idx - oo * (CCHUNK * 9);
            int cc  = rem / 9;
            int k   = rem - cc * 9;
            sw[cc][k][oo] = base[(((size_t)(og * 64 + oo)) * CC + (c0 + cc)) * 9 + k];
        }
        __syncthreads();

        for (int c = 0; c < CCHUNK; c++) {
            // cache 6x6 input patch in registers
            float xr[6][6];
            #pragma unroll
            for (int r = 0; r < 6; r++) {
                float4 v4 = *(const float4*)&sx[c][pr + r][pc];
                xr[r][0] = v4.x; xr[r][1] = v4.y; xr[r][2] = v4.z; xr[r][3] = v4.w;
                xr[r][4] = sx[c][pr + r][pc + 4];
                xr[r][5] = sx[c][pr + r][pc + 5];
            }
            #pragma unroll
            for (int ky = 0; ky < 3; ky++) {
                #pragma unroll
                for (int kx = 0; kx < 3; kx++) {
                    const int k = ky * 3 + kx;
                    float w0 = sw[c][k][to * 4 + 0];
                    float w1 = sw[c][k][to * 4 + 1];
                    float w2 = sw[c][k][to * 4 + 2];
                    float w3 = sw[c][k][to * 4 + 3];
                    #pragma unroll
                    for (int dr = 0; dr < 4; dr++) {
                        #pragma unroll
                        for (int dc = 0; dc < 4; dc++) {
                            float xv = xr[dr + ky][dc + kx];
                            acc[0][dr][dc] = fmaf(w0, xv, acc[0][dr][dc]);
                            acc[1][dr][dc] = fmaf(w1, xv, acc[1][dr][dc]);
                            acc[2][dr][dc] = fmaf(w2, xv, acc[2][dr][dc]);
                            acc[3][dr][dc] = fmaf(w3, xv, acc[3][dr][dc]);
                        }
                    }
                }
            }
        }
    }

    // epilogue: scale by g[b,o] and store (float4 rows)
    #pragma unroll
    for (int j = 0; j < 4; j++) {
        int o = og * 64 + to * 4 + j;
        float gv = d_g[b * OO + o];
        #pragma unroll
        for (int dr = 0; dr < 4; dr++) {
            int oh = th0 + pr + dr;
            float4 v;
            v.x = acc[j][dr][0] * gv;
            v.y = acc[j][dr][1] * gv;
            v.z = acc[j][dr][2] * gv;
            v.w = acc[j][dr][3] * gv;
            *(float4*)&out[(((size_t)b * OO + o) * HH + oh) * WW + tw0 + pc] = v;
        }
    }
}

// ---------------------------------------------------------------------------
extern "C" void kernel_launch(void* const* d_in, const int* in_sizes, int n_in,
                              void* d_out, int out_size) {
    // Defensive: match inputs by element count (all five are distinct).
    const float *x = nullptr, *w = nullptr, *bw = nullptr, *mw = nullptr, *mb = nullptr;
    for (int i = 0; i < n_in; i++) {
        switch (in_sizes[i]) {
            case BB * CC * HH * WW: x  = (const float*)d_in[i]; break; // 8388608
            case BB * 512:          w  = (const float*)d_in[i]; break; // 4096
            case OO * CC * 9:       bw = (const float*)d_in[i]; break; // 2359296
            case OO * CC:           mw = (const float*)d_in[i]; break; // 262144
            case CC:                mb = (const float*)d_in[i]; break; // 512
        }
    }
    float* out = (float*)d_out;

    s_kernel<<<(BB * CC * 32 + 255) / 256, 256>>>(w, mw, mb);
    w2_kernel<<<(OO * CC + 255) / 256, 256>>>(bw);
    g_kernel<<<(BB * OO * 32 + 255) / 256, 256>>>();
    xs_kernel<<<((BB * CC * HH * WW) / 4 + 255) / 256, 256>>>(x);

    dim3 grid(16, 8, 8);  // 16 spatial tiles x 8 o-groups x 8 batch
    conv_kernel<<<grid, 256>>>(bw, out);
}

// round 5
// speedup vs baseline: 2.8151x; 2.8151x over previous
#include <cuda_runtime.h>
#include <cstdint>

// ---------------- problem constants ----------------
#define BB 8
#define CC 512
#define OO 512
#define HH 64
#define WW 64
#define MOD_SCALE_F 0.04419417382415922f   // 1/sqrt(512)

// padded flat grid: width 72, height 66
#define WP 72
#define QTOT (WP * 66)        // 4752
#define NQT 36                // q tiles of 128 covering [72, 4680)
#define ROWSB 274             // 128 + 2*73 halo rows
#define NSTEP 144             // 16 c-chunks * 9 taps

// SMEM float offsets (stride 40 floats per row)
#define SA0 0
#define SA1 5120              // 128*40
#define SB0 10240
#define SB1 21200             // +274*40
#define SMEM_DYN (32160 * 4)  // 128640 B

// ---------------- device scratch ----------------
__device__ float    d_s[BB * CC];
__device__ float    d_W2[OO * CC];
__device__ float    d_g[BB * OO];
__device__ uint32_t d_xsp[(size_t)BB * QTOT * CC];  // padded NHWC, tf32-rounded bits
__device__ uint32_t d_Wp2[(size_t)9 * OO * CC];     // [t][j][o][c32] staging layout

__device__ __forceinline__ uint32_t f2tf32(float f) {
    uint32_t u;
    asm("cvt.rna.tf32.f32 %0, %1;" : "=r"(u) : "f"(f));
    return u;
}

__device__ __forceinline__ void mma1688(float* d, uint32_t a0, uint32_t a1,
                                        uint32_t a2, uint32_t a3,
                                        uint32_t b0, uint32_t b1) {
    asm volatile(
        "mma.sync.aligned.m16n8k8.row.col.f32.tf32.tf32.f32 "
        "{%0,%1,%2,%3}, {%4,%5,%6,%7}, {%8,%9}, {%0,%1,%2,%3};"
        : "+f"(d[0]), "+f"(d[1]), "+f"(d[2]), "+f"(d[3])
        : "r"(a0), "r"(a1), "r"(a2), "r"(a3), "r"(b0), "r"(b1));
}

// pair-permute 8 consecutive c into (c0,c4,c1,c5) (c2,c6,c3,c7)
__device__ __forceinline__ uint4 perm0(uint4 x, uint4 y) {
    return make_uint4(x.x, y.x, x.y, y.y);
}
__device__ __forceinline__ uint4 perm1(uint4 x, uint4 y) {
    return make_uint4(x.z, y.z, x.w, y.w);
}

// ---------------- stage 1: s[b,c] ----------------
__global__ void s_kernel(const float* __restrict__ w, const float* __restrict__ mw,
                         const float* __restrict__ mb) {
    int gid = blockIdx.x * blockDim.x + threadIdx.x;
    int wid = gid >> 5, lane = gid & 31;
    if (wid >= BB * CC) return;
    int b = wid >> 9, c = wid & 511;
    const float* wr = w + b * 512;
    const float* mr = mw + c * 512;
    float acc = 0.f;
    #pragma unroll 4
    for (int d = lane; d < 512; d += 32) acc = fmaf(wr[d], mr[d], acc);
    #pragma unroll
    for (int o = 16; o; o >>= 1) acc += __shfl_xor_sync(0xffffffffu, acc, o);
    if (lane == 0) d_s[wid] = acc * MOD_SCALE_F + mb[c] + 1.0f;
}

// ---------------- stage 2: W2[o,c] ----------------
__global__ void w2_kernel(const float* __restrict__ bw) {
    int i = blockIdx.x * blockDim.x + threadIdx.x;
    if (i >= OO * CC) return;
    const float* p = bw + (size_t)i * 9;
    float a = 0.f;
    #pragma unroll
    for (int k = 0; k < 9; k++) { float v = p[k]; a = fmaf(v, v, a); }
    d_W2[i] = a;
}

// ---------------- stage 3: g[b,o] ----------------
__global__ void g_kernel() {
    int gid = blockIdx.x * blockDim.x + threadIdx.x;
    int wid = gid >> 5, lane = gid & 31;
    if (wid >= BB * OO) return;
    int b = wid >> 9, o = wid & 511;
    const float* sr = d_s + b * 512;
    const float* w2 = d_W2 + o * 512;
    float acc = 0.f;
    #pragma unroll 4
    for (int c = lane; c < 512; c += 32) { float sv = sr[c]; acc = fmaf(sv * sv, w2[c], acc); }
    #pragma unroll
    for (int o2 = 16; o2; o2 >>= 1) acc += __shfl_xor_sync(0xffffffffu, acc, o2);
    if (lane == 0) d_g[wid] = rsqrtf(acc);
}

// ---------------- stage 4a: modulated NCHW -> padded NHWC (tf32 bits) ----------
__global__ void xspad_kernel(const float* __restrict__ x) {
    __shared__ float t[32][33];
    int tid = threadIdx.x;
    int b = blockIdx.z, h = blockIdx.y;
    int wt = blockIdx.x & 1, ct = blockIdx.x >> 1;
    int c0 = ct * 32, w0 = wt * 32;
    int a = tid & 31, bb2 = tid >> 5;
    #pragma unroll
    for (int i = 0; i < 4; i++) {
        int c = bb2 + i * 8;
        t[c][a] = x[(((size_t)b * CC + c0 + c) * HH + h) * WW + w0 + a] * d_s[b * CC + c0 + c];
    }
    __syncthreads();
    #pragma unroll
    for (int i = 0; i < 4; i++) {
        int w = bb2 + i * 8;
        d_xsp[((size_t)b * QTOT + (h + 1) * WP + w0 + w) * CC + c0 + a] = f2tf32(t[a][w]);
    }
}

// ---------------- stage 4b: zero pad cells ----------------
__global__ void padzero_kernel() {
    int i = blockIdx.x * blockDim.x + threadIdx.x;   // BB*656*128 uint4s
    if (i >= BB * 656 * 128) return;
    int b = i / (656 * 128);
    int rem = i - b * (656 * 128);
    int p = rem >> 7, f = rem & 127;
    int q;
    if (p < 72) q = p;
    else if (p < 144) q = 4680 + (p - 72);
    else { int p2 = p - 144; q = (1 + (p2 >> 3)) * WP + 64 + (p2 & 7); }
    *(uint4*)(d_xsp + ((size_t)b * QTOT + q) * CC + f * 4) = make_uint4(0u, 0u, 0u, 0u);
}

// ---------------- stage 5: pack weights to staging layout (tf32 bits) --------
// d_Wp2[((t*16 + j)*512 + o)*32 + cc] = tf32(base[o][j*32+cc][t])
__global__ void wpack_kernel(const float* __restrict__ bw) {
    size_t i = (size_t)blockIdx.x * 256 + threadIdx.x;
    if (i >= (size_t)9 * 512 * 512) return;
    int cc = (int)(i & 31);
    size_t r = i >> 5;
    int o = (int)(r & 511); r >>= 9;
    int j = (int)(r & 15);
    int t = (int)(r >> 4);
    float v = bw[((size_t)o * 512 + j * 32 + cc) * 9 + t];
    d_Wp2[i] = f2tf32(v);
}

// ---------------- stage 6: mma.sync tf32 implicit-GEMM conv ----------------
__global__ __launch_bounds__(256, 1) void conv_mma_kernel(float* __restrict__ out) {
    extern __shared__ uint32_t smem_u[];
    const int tid = threadIdx.x;
    const int wid = tid >> 5, lane = tid & 31;
    const int mw = wid & 1, nw = wid >> 1;     // o-warp (2), q-warp (4)
    const int g = lane >> 2, t4 = lane & 3;
    const int tile = blockIdx.x, og = blockIdx.y, b = blockIdx.z;
    const int q0 = 72 + 128 * tile;
    const int qb = q0 - 73;
    const int o0 = og * 128;

    const int DT[9] = {-73, -72, -71, -1, 0, 1, 71, 72, 73};

    float acc[4][4][4];
    #pragma unroll
    for (int mt = 0; mt < 4; mt++)
        #pragma unroll
        for (int nt = 0; nt < 4; nt++)
            #pragma unroll
            for (int r = 0; r < 4; r++) acc[mt][nt][r] = 0.f;

    const uint4 z4 = make_uint4(0u, 0u, 0u, 0u);
    const uint4* xB = (const uint4*)d_xsp + (size_t)b * QTOT * 128;

    // prologue: A step 0 into SA0
    {
        const uint4* srcA = (const uint4*)d_Wp2 + ((size_t)(0 * 16 + 0) * 512 + o0) * 8;
        #pragma unroll
        for (int p = 0; p < 2; p++) {
            int idx = tid + p * 256;              // 0..511 8c-units
            int o = idx >> 2, u = idx & 3;
            uint4 v0 = srcA[o * 8 + u * 2];
            uint4 v1 = srcA[o * 8 + u * 2 + 1];
            *(uint4*)&smem_u[SA0 + o * 40 + u * 8]     = perm0(v0, v1);
            *(uint4*)&smem_u[SA0 + o * 40 + u * 8 + 4] = perm1(v0, v1);
        }
        // B chunk 0 into SB0
        for (int it = 0; it < 5; it++) {
            int idx = tid + it * 256;
            if (idx < ROWSB * 4) {
                int r = idx >> 2, u = idx & 3;
                int gq = qb + r;
                uint4 v0 = z4, v1 = z4;
                if (gq >= 0 && gq < QTOT) {
                    const uint4* srcB = xB + (size_t)gq * 128;   // j=0
                    v0 = srcB[u * 2]; v1 = srcB[u * 2 + 1];
                }
                *(uint4*)&smem_u[SB0 + r * 40 + u * 8]     = perm0(v0, v1);
                *(uint4*)&smem_u[SB0 + r * 40 + u * 8 + 4] = perm1(v0, v1);
            }
        }
    }
    __syncthreads();

    for (int s = 0; s < NSTEP; s++) {
        const int sn = s + 1;
        const bool doA = sn < NSTEP;
        uint4 apf[2][2];
        if (doA) {
            const int tn = sn % 9, jn = sn / 9;
            const uint4* srcA = (const uint4*)d_Wp2 + ((size_t)(tn * 16 + jn) * 512 + o0) * 8;
            #pragma unroll
            for (int p = 0; p < 2; p++) {
                int idx = tid + p * 256;
                int o = idx >> 2, u = idx & 3;
                apf[p][0] = srcA[o * 8 + u * 2];
                apf[p][1] = srcA[o * 8 + u * 2 + 1];
            }
        }
        const int jB = s / 9 + 1, prt = s % 9;
        const int rB = prt * 31 + (tid >> 2), uB = tid & 3;
        const bool doB = (jB < 16) && (tid < 124) && (rB < ROWSB);
        uint4 bpf0 = z4, bpf1 = z4;
        if (doB) {
            int gq = qb + rB;
            if (gq >= 0 && gq < QTOT) {
                const uint4* srcB = xB + (size_t)gq * 128 + jB * 8;
                bpf0 = srcB[uB * 2]; bpf1 = srcB[uB * 2 + 1];
            }
        }

        // ---- compute on buffers of step s ----
        const uint32_t* sa  = smem_u + ((s & 1) ? SA1 : SA0);
        const uint32_t* sbp = smem_u + (((s / 9) & 1) ? SB1 : SB0);
        const int dt = DT[s % 9];
        const int qB0 = 73 + dt + nw * 32 + g;
        #pragma unroll
        for (int ks = 0; ks < 4; ks++) {
            const int k0 = ks * 8 + t4 * 2;
            uint2 afl[4], afh[4];
            #pragma unroll
            for (int mt = 0; mt < 4; mt++) {
                int r0 = mw * 64 + mt * 16 + g;
                afl[mt] = *(const uint2*)&sa[r0 * 40 + k0];
                afh[mt] = *(const uint2*)&sa[(r0 + 8) * 40 + k0];
            }
            #pragma unroll
            for (int nt = 0; nt < 4; nt++) {
                uint2 bf = *(const uint2*)&sbp[(qB0 + nt * 8) * 40 + k0];
                #pragma unroll
                for (int mt = 0; mt < 4; mt++)
                    mma1688(acc[mt][nt], afl[mt].x, afh[mt].x, afl[mt].y, afh[mt].y,
                            bf.x, bf.y);
            }
        }

        // ---- stores of prefetched step s+1 ----
        if (doA) {
            uint32_t* dA = smem_u + ((sn & 1) ? SA1 : SA0);
            #pragma unroll
            for (int p = 0; p < 2; p++) {
                int idx = tid + p * 256;
                int o = idx >> 2, u = idx & 3;
                *(uint4*)&dA[o * 40 + u * 8]     = perm0(apf[p][0], apf[p][1]);
                *(uint4*)&dA[o * 40 + u * 8 + 4] = perm1(apf[p][0], apf[p][1]);
            }
        }
        if (doB) {
            uint32_t* dB = smem_u + ((jB & 1) ? SB1 : SB0);
            *(uint4*)&dB[rB * 40 + uB * 8]     = perm0(bpf0, bpf1);
            *(uint4*)&dB[rB * 40 + uB * 8 + 4] = perm1(bpf0, bpf1);
        }
        __syncthreads();
    }

    // ---- epilogue: SMEM transpose, scale by g, float4 stores ----
    float* eb = (float*)smem_u;   // 64 x 132
    #pragma unroll 1
    for (int r = 0; r < 2; r++) {
        __syncthreads();
        if (mw == r) {
            #pragma unroll
            for (int mt = 0; mt < 4; mt++)
                #pragma unroll
                for (int nt = 0; nt < 4; nt++) {
                    int row = mt * 16 + g;
                    int col = nw * 32 + nt * 8 + 2 * t4;
                    eb[row * 132 + col]           = acc[mt][nt][0];
                    eb[row * 132 + col + 1]       = acc[mt][nt][1];
                    eb[(row + 8) * 132 + col]     = acc[mt][nt][2];
                    eb[(row + 8) * 132 + col + 1] = acc[mt][nt][3];
                }
        }
        __syncthreads();
        for (int i = tid; i < 64 * 32; i += 256) {
            int ol = i >> 5, q4 = i & 31;
            int q = q0 + q4 * 4;
            int qr = q / WP, qc = q - qr * WP;
            if (qc < 64) {
                float4 v = *(float4*)&eb[ol * 132 + q4 * 4];
                int o = o0 + r * 64 + ol;
                float gv = d_g[b * OO + o];
                v.x *= gv; v.y *= gv; v.z *= gv; v.w *= gv;
                *(float4*)&out[(((size_t)b * OO + o) * 64 + qr - 1) * 64 + qc] = v;
            }
        }
    }
}

// ---------------- launch ----------------
extern "C" void kernel_launch(void* const* d_in, const int* in_sizes, int n_in,
                              void* d_out, int out_size) {
    const float *x = nullptr, *w = nullptr, *bw = nullptr, *mw = nullptr, *mb = nullptr;
    for (int i = 0; i < n_in; i++) {
        switch (in_sizes[i]) {
            case BB * CC * HH * WW: x  = (const float*)d_in[i]; break;
            case BB * 512:          w  = (const float*)d_in[i]; break;
            case OO * CC * 9:       bw = (const float*)d_in[i]; break;
            case OO * CC:           mw = (const float*)d_in[i]; break;
            case CC:                mb = (const float*)d_in[i]; break;
        }
    }
    float* out = (float*)d_out;

    cudaFuncSetAttribute(conv_mma_kernel, cudaFuncAttributeMaxDynamicSharedMemorySize, SMEM_DYN);

    s_kernel<<<(BB * CC * 32 + 255) / 256, 256>>>(w, mw, mb);
    w2_kernel<<<(OO * CC + 255) / 256, 256>>>(bw);
    g_kernel<<<(BB * OO * 32 + 255) / 256, 256>>>();
    xspad_kernel<<<dim3(32, 64, 8), 256>>>(x);
    padzero_kernel<<<(BB * 656 * 128 + 255) / 256, 256>>>();
    wpack_kernel<<<(int)(((size_t)9 * 512 * 512 + 255) / 256), 256>>>(bw);

    conv_mma_kernel<<<dim3(NQT, 4, BB), 256, SMEM_DYN>>>(out);
}

// round 6
// speedup vs baseline: 4.5443x; 1.6142x over previous
#include <cuda_runtime.h>
#include <cuda_fp16.h>
#include <cstdint>

// ---------------- problem constants ----------------
#define BB 8
#define CC 512
#define OO 512
#define HH 64
#define WW 64
#define MOD_SCALE_F 0.04419417382415922f   // 1/sqrt(512)

// padded flat grid: width 72, height 66
#define WP 72
#define QTOT (WP * 66)        // 4752
#define NQT 36                // q tiles of 128 covering [72, 4680)
#define ROWSB 274             // 128 + 2*73 halo rows
#define NSTEP 144             // 16 c-chunks * 9 taps

// SMEM b32 offsets, row stride 20 b32 (16 data + 4 pad)
#define SROW 20
#define SA0 0
#define SA1 (128 * SROW)              // 2560
#define SB0 (2 * 128 * SROW)          // 5120
#define SB1 (SB0 + ROWSB * SROW)      // 10600
#define SMEM_DYN ((SB1 + ROWSB * SROW) * 4)   // 64320 B

// ---------------- device scratch ----------------
__device__ float    d_s[BB * CC];
__device__ float    d_W2[OO * CC];
__device__ float    d_g[BB * OO];
__device__ __half   d_xsph[(size_t)BB * QTOT * CC];        // padded NHWC fp16
__device__ uint32_t d_Wp2u[(size_t)9 * 16 * 512 * 16];     // [t][j][o][w] half2 pairs

__device__ __forceinline__ void mma16816(float* d, uint32_t a0, uint32_t a1,
                                         uint32_t a2, uint32_t a3,
                                         uint32_t b0, uint32_t b1) {
    asm volatile(
        "mma.sync.aligned.m16n8k16.row.col.f32.f16.f16.f32 "
        "{%0,%1,%2,%3}, {%4,%5,%6,%7}, {%8,%9}, {%0,%1,%2,%3};"
        : "+f"(d[0]), "+f"(d[1]), "+f"(d[2]), "+f"(d[3])
        : "r"(a0), "r"(a1), "r"(a2), "r"(a3), "r"(b0), "r"(b1));
}

// pair-permute 8 b32 (w0..w7) into (w0,w4,w1,w5) (w2,w6,w3,w7)
__device__ __forceinline__ uint4 perm0(uint4 x, uint4 y) {
    return make_uint4(x.x, y.x, x.y, y.y);
}
__device__ __forceinline__ uint4 perm1(uint4 x, uint4 y) {
    return make_uint4(x.z, y.z, x.w, y.w);
}

// ---------------- stage 1: s[b,c] ----------------
__global__ void s_kernel(const float* __restrict__ w, const float* __restrict__ mw,
                         const float* __restrict__ mb) {
    int gid = blockIdx.x * blockDim.x + threadIdx.x;
    int wid = gid >> 5, lane = gid & 31;
    if (wid >= BB * CC) return;
    int b = wid >> 9, c = wid & 511;
    const float* wr = w + b * 512;
    const float* mr = mw + c * 512;
    float acc = 0.f;
    #pragma unroll 4
    for (int d = lane; d < 512; d += 32) acc = fmaf(wr[d], mr[d], acc);
    #pragma unroll
    for (int o = 16; o; o >>= 1) acc += __shfl_xor_sync(0xffffffffu, acc, o);
    if (lane == 0) d_s[wid] = acc * MOD_SCALE_F + mb[c] + 1.0f;
}

// ---------------- stage 2: W2[o,c] ----------------
__global__ void w2_kernel(const float* __restrict__ bw) {
    int i = blockIdx.x * blockDim.x + threadIdx.x;
    if (i >= OO * CC) return;
    const float* p = bw + (size_t)i * 9;
    float a = 0.f;
    #pragma unroll
    for (int k = 0; k < 9; k++) { float v = p[k]; a = fmaf(v, v, a); }
    d_W2[i] = a;
}

// ---------------- stage 3: g[b,o] ----------------
__global__ void g_kernel() {
    int gid = blockIdx.x * blockDim.x + threadIdx.x;
    int wid = gid >> 5, lane = gid & 31;
    if (wid >= BB * OO) return;
    int b = wid >> 9, o = wid & 511;
    const float* sr = d_s + b * 512;
    const float* w2 = d_W2 + o * 512;
    float acc = 0.f;
    #pragma unroll 4
    for (int c = lane; c < 512; c += 32) { float sv = sr[c]; acc = fmaf(sv * sv, w2[c], acc); }
    #pragma unroll
    for (int o2 = 16; o2; o2 >>= 1) acc += __shfl_xor_sync(0xffffffffu, acc, o2);
    if (lane == 0) d_g[wid] = rsqrtf(acc);
}

// ---------------- stage 4a: modulated NCHW -> padded NHWC fp16 ----------------
__global__ void xspad_kernel(const float* __restrict__ x) {
    __shared__ float t[32][33];
    int tid = threadIdx.x;
    int b = blockIdx.z, h = blockIdx.y;
    int wt = blockIdx.x & 1, ct = blockIdx.x >> 1;
    int c0 = ct * 32, w0 = wt * 32;
    int a = tid & 31, bb2 = tid >> 5;
    #pragma unroll
    for (int i = 0; i < 4; i++) {
        int c = bb2 + i * 8;
        t[c][a] = x[(((size_t)b * CC + c0 + c) * HH + h) * WW + w0 + a] * d_s[b * CC + c0 + c];
    }
    __syncthreads();
    #pragma unroll
    for (int i = 0; i < 4; i++) {
        int w = bb2 + i * 8;
        d_xsph[((size_t)b * QTOT + (h + 1) * WP + w0 + w) * CC + c0 + a] =
            __float2half_rn(t[a][w]);
    }
}

// ---------------- stage 4b: zero pad cells ----------------
__global__ void padzero_kernel() {
    int i = blockIdx.x * blockDim.x + threadIdx.x;   // BB*656*64 uint4 (8 halves each)
    if (i >= BB * 656 * 64) return;
    int b = i / (656 * 64);
    int rem = i - b * (656 * 64);
    int p = rem >> 6, f = rem & 63;
    int q;
    if (p < 72) q = p;
    else if (p < 144) q = 4680 + (p - 72);
    else { int p2 = p - 144; q = (1 + (p2 >> 3)) * WP + 64 + (p2 & 7); }
    ((uint4*)d_xsph)[((size_t)b * QTOT + q) * 64 + f] = make_uint4(0u, 0u, 0u, 0u);
}

// ---------------- stage 5: pack weights as half2 pairs ----------------
// d_Wp2u[((t*16+j)*512+o)*16 + w] = half2(base[o][j*32+2w][t], base[o][j*32+2w+1][t])
__global__ void wpack_kernel(const float* __restrict__ bw) {
    size_t i = (size_t)blockIdx.x * 256 + threadIdx.x;
    if (i >= (size_t)9 * 16 * 512 * 16) return;
    int w = (int)(i & 15);
    int o = (int)((i >> 4) & 511);
    int j = (int)((i >> 13) & 15);
    int t = (int)(i >> 17);
    float v0 = bw[((size_t)o * 512 + j * 32 + 2 * w) * 9 + t];
    float v1 = bw[((size_t)o * 512 + j * 32 + 2 * w + 1) * 9 + t];
    __half2 h = __floats2half2_rn(v0, v1);
    d_Wp2u[i] = *(uint32_t*)&h;
}

// ---------------- stage 6: fp16 mma.sync implicit-GEMM conv ----------------
__global__ __launch_bounds__(256, 2) void conv_mma_kernel(float* __restrict__ out) {
    extern __shared__ uint32_t smem_u[];
    const int tid = threadIdx.x;
    const int wid = tid >> 5, lane = tid & 31;
    const int mw = wid & 1, nw = wid >> 1;     // o-warp (2), q-warp (4)
    const int g = lane >> 2, t4 = lane & 3;
    const int tile = blockIdx.x, og = blockIdx.y, b = blockIdx.z;
    const int q0 = 72 + 128 * tile;
    const int qb = q0 - 73;
    const int o0 = og * 128;

    const int DT[9] = {-73, -72, -71, -1, 0, 1, 71, 72, 73};

    float acc[4][4][4];
    #pragma unroll
    for (int mt = 0; mt < 4; mt++)
        #pragma unroll
        for (int nt = 0; nt < 4; nt++)
            #pragma unroll
            for (int r = 0; r < 4; r++) acc[mt][nt][r] = 0.f;

    const uint4 z4 = make_uint4(0u, 0u, 0u, 0u);
    const uint4* xB = (const uint4*)d_xsph + (size_t)b * QTOT * 64;

    const int oA = tid >> 1, gA = tid & 1;

    // prologue: A step 0, B chunk 0
    {
        const uint4* srcA = (const uint4*)d_Wp2u + ((size_t)(o0 + oA)) * 4 + gA * 2;
        uint4 v0 = srcA[0], v1 = srcA[1];
        *(uint4*)&smem_u[SA0 + oA * SROW + gA * 8]     = perm0(v0, v1);
        *(uint4*)&smem_u[SA0 + oA * SROW + gA * 8 + 4] = perm1(v0, v1);
        for (int it = 0; it < 3; it++) {
            int idx = tid + it * 256;
            if (idx < ROWSB * 2) {
                int r = idx >> 1, gB = idx & 1;
                int gq = qb + r;
                uint4 b0 = z4, b1 = z4;
                if (gq >= 0 && gq < QTOT) {
                    const uint4* srcB = xB + (size_t)gq * 64 + gB * 2;   // j=0
                    b0 = srcB[0]; b1 = srcB[1];
                }
                *(uint4*)&smem_u[SB0 + r * SROW + gB * 8]     = perm0(b0, b1);
                *(uint4*)&smem_u[SB0 + r * SROW + gB * 8 + 4] = perm1(b0, b1);
            }
        }
    }
    __syncthreads();

    for (int s = 0; s < NSTEP; s++) {
        const int sn = s + 1;
        const bool doA = sn < NSTEP;
        uint4 av0, av1;
        if (doA) {
            const int tn = sn % 9, jn = sn / 9;
            const uint4* srcA = (const uint4*)d_Wp2u +
                ((size_t)(tn * 16 + jn) * 512 + o0 + oA) * 4 + gA * 2;
            av0 = srcA[0]; av1 = srcA[1];
        }
        // incremental B staging for chunk jB (62 row-halves per step)
        const int jB = s / 9 + 1, prt = s % 9;
        const int unit = prt * 62 + tid;
        const int rB = unit >> 1, gB = unit & 1;
        const bool doB = (jB < 16) && (tid < 62) && (rB < ROWSB);
        uint4 bv0 = z4, bv1 = z4;
        if (doB) {
            int gq = qb + rB;
            if (gq >= 0 && gq < QTOT) {
                const uint4* srcB = xB + (size_t)gq * 64 + jB * 4 + gB * 2;
                bv0 = srcB[0]; bv1 = srcB[1];
            }
        }

        // ---- compute on buffers of step s ----
        const uint32_t* sa  = smem_u + ((s & 1) ? SA1 : SA0);
        const uint32_t* sbp = smem_u + (((s / 9) & 1) ? SB1 : SB0);
        const int dt = DT[s % 9];
        const int qB0 = 73 + dt + nw * 32 + g;
        #pragma unroll
        for (int ks = 0; ks < 2; ks++) {
            const int pos = ks * 8 + 2 * t4;
            uint2 al[4], ah[4];
            #pragma unroll
            for (int mt = 0; mt < 4; mt++) {
                int r0 = mw * 64 + mt * 16 + g;
                al[mt] = *(const uint2*)&sa[r0 * SROW + pos];
                ah[mt] = *(const uint2*)&sa[(r0 + 8) * SROW + pos];
            }
            #pragma unroll
            for (int nt = 0; nt < 4; nt++) {
                uint2 bf = *(const uint2*)&sbp[(qB0 + nt * 8) * SROW + pos];
                #pragma unroll
                for (int mt = 0; mt < 4; mt++)
                    mma16816(acc[mt][nt], al[mt].x, ah[mt].x, al[mt].y, ah[mt].y,
                             bf.x, bf.y);
            }
        }

        // ---- stores of prefetched step s+1 ----
        if (doA) {
            uint32_t* dA = smem_u + ((sn & 1) ? SA1 : SA0);
            *(uint4*)&dA[oA * SROW + gA * 8]     = perm0(av0, av1);
            *(uint4*)&dA[oA * SROW + gA * 8 + 4] = perm1(av0, av1);
        }
        if (doB) {
            uint32_t* dB = smem_u + ((jB & 1) ? SB1 : SB0);
            *(uint4*)&dB[rB * SROW + gB * 8]     = perm0(bv0, bv1);
            *(uint4*)&dB[rB * SROW + gB * 8 + 4] = perm1(bv0, bv1);
        }
        __syncthreads();
    }

    // ---- epilogue: SMEM transpose, scale by g, float4 stores ----
    float* eb = (float*)smem_u;   // 64 x 132
    #pragma unroll 1
    for (int r = 0; r < 2; r++) {
        __syncthreads();
        if (mw == r) {
            #pragma unroll
            for (int mt = 0; mt < 4; mt++)
                #pragma unroll
                for (int nt = 0; nt < 4; nt++) {
                    int row = mt * 16 + g;
                    int col = nw * 32 + nt * 8 + 2 * t4;
                    eb[row * 132 + col]           = acc[mt][nt][0];
                    eb[row * 132 + col + 1]       = acc[mt][nt][1];
                    eb[(row + 8) * 132 + col]     = acc[mt][nt][2];
                    eb[(row + 8) * 132 + col + 1] = acc[mt][nt][3];
                }
        }
        __syncthreads();
        for (int i = tid; i < 64 * 32; i += 256) {
            int ol = i >> 5, q4 = i & 31;
            int q = q0 + q4 * 4;
            int qr = q / WP, qc = q - qr * WP;
            if (qc < 64) {
                float4 v = *(float4*)&eb[ol * 132 + q4 * 4];
                int o = o0 + r * 64 + ol;
                float gv = d_g[b * OO + o];
                v.x *= gv; v.y *= gv; v.z *= gv; v.w *= gv;
                *(float4*)&out[(((size_t)b * OO + o) * 64 + qr - 1) * 64 + qc] = v;
            }
        }
    }
}

// ---------------- launch ----------------
extern "C" void kernel_launch(void* const* d_in, const int* in_sizes, int n_in,
                              void* d_out, int out_size) {
    const float *x = nullptr, *w = nullptr, *bw = nullptr, *mw = nullptr, *mb = nullptr;
    for (int i = 0; i < n_in; i++) {
        switch (in_sizes[i]) {
            case BB * CC * HH * WW: x  = (const float*)d_in[i]; break;
            case BB * 512:          w  = (const float*)d_in[i]; break;
            case OO * CC * 9:       bw = (const float*)d_in[i]; break;
            case OO * CC:           mw = (const float*)d_in[i]; break;
            case CC:                mb = (const float*)d_in[i]; break;
        }
    }
    float* out = (float*)d_out;

    cudaFuncSetAttribute(conv_mma_kernel, cudaFuncAttributeMaxDynamicSharedMemorySize, SMEM_DYN);

    s_kernel<<<(BB * CC * 32 + 255) / 256, 256>>>(w, mw, mb);
    w2_kernel<<<(OO * CC + 255) / 256, 256>>>(bw);
    g_kernel<<<(BB * OO * 32 + 255) / 256, 256>>>();
    xspad_kernel<<<dim3(32, 64, 8), 256>>>(x);
    padzero_kernel<<<(BB * 656 * 64 + 255) / 256, 256>>>();
    wpack_kernel<<<(int)(((size_t)9 * 16 * 512 * 16 + 255) / 256), 256>>>(bw);

    conv_mma_kernel<<<dim3(NQT, 4, BB), 256, SMEM_DYN>>>(out);
}

// round 7
// speedup vs baseline: 6.3442x; 1.3961x over previous
#include <cuda_runtime.h>
#include <cuda_fp16.h>
#include <cstdint>

// ---------------- problem constants ----------------
#define BB 8
#define CC 512
#define OO 512
#define HH 64
#define WW 64
#define MOD_SCALE_F 0.04419417382415922f   // 1/sqrt(512)

// padded flat grid: width 72, height 66
#define WP 72
#define QTOT (WP * 66)        // 4752
#define NQT 36                // q tiles of 128 covering [72, 4680)
#define ROWSB 274             // 128 + 2*73 halo rows
#define NSTEP 144             // 16 c-chunks * 9 taps

// SMEM b32 offsets, row stride 20 b32 (80 B: 64 B data + 16 B pad, coprime banks)
#define SROW 20
#define SA0 0
#define SA1 (128 * SROW)              // 2560
#define SB0 (2 * 128 * SROW)          // 5120
#define SB1 (SB0 + ROWSB * SROW)      // 10600
#define SMEM_DYN ((SB1 + ROWSB * SROW) * 4)   // 64320 B

// ---------------- device scratch ----------------
__device__ float    d_s[BB * CC];
__device__ float    d_W2[OO * CC];
__device__ float    d_g[BB * OO];
__device__ __half   d_xsph[(size_t)BB * QTOT * CC];        // padded NHWC fp16
__device__ uint32_t d_Wp2u[(size_t)9 * 16 * 512 * 16];     // [t][j][o][c-pair] half2

__device__ __forceinline__ void mma16816(float* d, uint32_t a0, uint32_t a1,
                                         uint32_t a2, uint32_t a3,
                                         uint32_t b0, uint32_t b1) {
    asm volatile(
        "mma.sync.aligned.m16n8k16.row.col.f32.f16.f16.f32 "
        "{%0,%1,%2,%3}, {%4,%5,%6,%7}, {%8,%9}, {%0,%1,%2,%3};"
        : "+f"(d[0]), "+f"(d[1]), "+f"(d[2]), "+f"(d[3])
        : "r"(a0), "r"(a1), "r"(a2), "r"(a3), "r"(b0), "r"(b1));
}

__device__ __forceinline__ void ldsm_x4(uint32_t& r0, uint32_t& r1,
                                        uint32_t& r2, uint32_t& r3, uint32_t addr) {
    asm volatile("ldmatrix.sync.aligned.m8n8.x4.shared.b16 {%0,%1,%2,%3}, [%4];"
                 : "=r"(r0), "=r"(r1), "=r"(r2), "=r"(r3) : "r"(addr));
}

__device__ __forceinline__ uint32_t smem_u32(const void* p) {
    uint32_t a;
    asm("{ .reg .u64 t; cvta.to.shared.u64 t, %1; cvt.u32.u64 %0, t; }" : "=r"(a) : "l"(p));
    return a;
}

// ---------------- stage 1: s[b,c] ----------------
__global__ void s_kernel(const float* __restrict__ w, const float* __restrict__ mw,
                         const float* __restrict__ mb) {
    int gid = blockIdx.x * blockDim.x + threadIdx.x;
    int wid = gid >> 5, lane = gid & 31;
    if (wid >= BB * CC) return;
    int b = wid >> 9, c = wid & 511;
    const float* wr = w + b * 512;
    const float* mr = mw + c * 512;
    float acc = 0.f;
    #pragma unroll 4
    for (int d = lane; d < 512; d += 32) acc = fmaf(wr[d], mr[d], acc);
    #pragma unroll
    for (int o = 16; o; o >>= 1) acc += __shfl_xor_sync(0xffffffffu, acc, o);
    if (lane == 0) d_s[wid] = acc * MOD_SCALE_F + mb[c] + 1.0f;
}

// ---------------- stage 2: W2[o,c] ----------------
__global__ void w2_kernel(const float* __restrict__ bw) {
    int i = blockIdx.x * blockDim.x + threadIdx.x;
    if (i >= OO * CC) return;
    const float* p = bw + (size_t)i * 9;
    float a = 0.f;
    #pragma unroll
    for (int k = 0; k < 9; k++) { float v = p[k]; a = fmaf(v, v, a); }
    d_W2[i] = a;
}

// ---------------- stage 3: g[b,o] ----------------
__global__ void g_kernel() {
    int gid = blockIdx.x * blockDim.x + threadIdx.x;
    int wid = gid >> 5, lane = gid & 31;
    if (wid >= BB * OO) return;
    int b = wid >> 9, o = wid & 511;
    const float* sr = d_s + b * 512;
    const float* w2 = d_W2 + o * 512;
    float acc = 0.f;
    #pragma unroll 4
    for (int c = lane; c < 512; c += 32) { float sv = sr[c]; acc = fmaf(sv * sv, w2[c], acc); }
    #pragma unroll
    for (int o2 = 16; o2; o2 >>= 1) acc += __shfl_xor_sync(0xffffffffu, acc, o2);
    if (lane == 0) d_g[wid] = rsqrtf(acc);
}

// ---------------- stage 4a: modulated NCHW -> padded NHWC fp16 ----------------
__global__ void xspad_kernel(const float* __restrict__ x) {
    __shared__ float t[32][33];
    int tid = threadIdx.x;
    int b = blockIdx.z, h = blockIdx.y;
    int wt = blockIdx.x & 1, ct = blockIdx.x >> 1;
    int c0 = ct * 32, w0 = wt * 32;
    int a = tid & 31, bb2 = tid >> 5;
    #pragma unroll
    for (int i = 0; i < 4; i++) {
        int c = bb2 + i * 8;
        t[c][a] = x[(((size_t)b * CC + c0 + c) * HH + h) * WW + w0 + a] * d_s[b * CC + c0 + c];
    }
    __syncthreads();
    #pragma unroll
    for (int i = 0; i < 4; i++) {
        int w = bb2 + i * 8;
        d_xsph[((size_t)b * QTOT + (h + 1) * WP + w0 + w) * CC + c0 + a] =
            __float2half_rn(t[a][w]);
    }
}

// ---------------- stage 4b: zero pad cells ----------------
__global__ void padzero_kernel() {
    int i = blockIdx.x * blockDim.x + threadIdx.x;   // BB*656*64 uint4 (8 halves each)
    if (i >= BB * 656 * 64) return;
    int b = i / (656 * 64);
    int rem = i - b * (656 * 64);
    int p = rem >> 6, f = rem & 63;
    int q;
    if (p < 72) q = p;
    else if (p < 144) q = 4680 + (p - 72);
    else { int p2 = p - 144; q = (1 + (p2 >> 3)) * WP + 64 + (p2 & 7); }
    ((uint4*)d_xsph)[((size_t)b * QTOT + q) * 64 + f] = make_uint4(0u, 0u, 0u, 0u);
}

// ---------------- stage 5: pack weights as half2 pairs ----------------
// d_Wp2u[((t*16+j)*512+o)*16 + w] = half2(base[o][j*32+2w][t], base[o][j*32+2w+1][t])
__global__ void wpack_kernel(const float* __restrict__ bw) {
    size_t i = (size_t)blockIdx.x * 256 + threadIdx.x;
    if (i >= (size_t)9 * 16 * 512 * 16) return;
    int w = (int)(i & 15);
    int o = (int)((i >> 4) & 511);
    int j = (int)((i >> 13) & 15);
    int t = (int)(i >> 17);
    float v0 = bw[((size_t)o * 512 + j * 32 + 2 * w) * 9 + t];
    float v1 = bw[((size_t)o * 512 + j * 32 + 2 * w + 1) * 9 + t];
    __half2 h = __floats2half2_rn(v0, v1);
    d_Wp2u[i] = *(uint32_t*)&h;
}

// ---------------- stage 6: fp16 mma.sync + ldmatrix implicit-GEMM conv --------
__global__ __launch_bounds__(256, 2) void conv_mma_kernel(float* __restrict__ out) {
    extern __shared__ uint32_t smem_u[];
    const uint32_t sbase = smem_u32(smem_u);
    const int tid = threadIdx.x;
    const int wid = tid >> 5, lane = tid & 31;
    const int mw = wid & 1, nw = wid >> 1;     // o-warp (2), q-warp (4)
    const int tile = blockIdx.x, og = blockIdx.y, b = blockIdx.z;
    const int q0 = 72 + 128 * tile;
    const int qb = q0 - 73;
    const int o0 = og * 128;

    const int DT[9] = {-73, -72, -71, -1, 0, 1, 71, 72, 73};

    // per-lane ldmatrix address components (bytes)
    const int aRowOff = (lane & 15) * 80 + (lane >> 4) * 16;        // A: row + k-half
    const int bRowOff = ((lane & 7) + ((lane & 16) >> 1)) * 80 + ((lane & 8) << 1);

    float acc[4][4][4];
    #pragma unroll
    for (int mt = 0; mt < 4; mt++)
        #pragma unroll
        for (int nt = 0; nt < 4; nt++)
            #pragma unroll
            for (int r = 0; r < 4; r++) acc[mt][nt][r] = 0.f;

    const uint4 z4 = make_uint4(0u, 0u, 0u, 0u);
    const uint4* xB = (const uint4*)d_xsph + (size_t)b * QTOT * 64;

    const int oA = tid >> 1, gA = tid & 1;

    // prologue: A step 0, B chunk 0 (plain contiguous layout)
    {
        const uint4* srcA = (const uint4*)d_Wp2u + ((size_t)(o0 + oA)) * 4 + gA * 2;
        uint4 v0 = srcA[0], v1 = srcA[1];
        *(uint4*)&smem_u[SA0 + oA * SROW + gA * 8]     = v0;
        *(uint4*)&smem_u[SA0 + oA * SROW + gA * 8 + 4] = v1;
        for (int it = 0; it < 3; it++) {
            int idx = tid + it * 256;
            if (idx < ROWSB * 2) {
                int r = idx >> 1, gB = idx & 1;
                int gq = qb + r;
                uint4 b0 = z4, b1 = z4;
                if (gq >= 0 && gq < QTOT) {
                    const uint4* srcB = xB + (size_t)gq * 64 + gB * 2;   // j=0
                    b0 = srcB[0]; b1 = srcB[1];
                }
                *(uint4*)&smem_u[SB0 + r * SROW + gB * 8]     = b0;
                *(uint4*)&smem_u[SB0 + r * SROW + gB * 8 + 4] = b1;
            }
        }
    }
    __syncthreads();

    for (int s = 0; s < NSTEP; s++) {
        const int sn = s + 1;
        const bool doA = sn < NSTEP;
        uint4 av0, av1;
        if (doA) {
            const int tn = sn % 9, jn = sn / 9;
            const uint4* srcA = (const uint4*)d_Wp2u +
                ((size_t)(tn * 16 + jn) * 512 + o0 + oA) * 4 + gA * 2;
            av0 = srcA[0]; av1 = srcA[1];
        }
        // incremental B staging for chunk jB
        const int jB = s / 9 + 1, prt = s % 9;
        const int unit = prt * 62 + tid;
        const int rB = unit >> 1, gB = unit & 1;
        const bool doB = (jB < 16) && (tid < 62) && (rB < ROWSB);
        uint4 bv0 = z4, bv1 = z4;
        if (doB) {
            int gq = qb + rB;
            if (gq >= 0 && gq < QTOT) {
                const uint4* srcB = xB + (size_t)gq * 64 + jB * 4 + gB * 2;
                bv0 = srcB[0]; bv1 = srcB[1];
            }
        }

        // ---- compute on buffers of step s ----
        const uint32_t saOff = ((s & 1) ? SA1 : SA0) * 4;
        const uint32_t sbOff = (((s / 9) & 1) ? SB1 : SB0) * 4;
        const int dt = DT[s % 9];
        const uint32_t aBase = sbase + saOff + (uint32_t)(mw * 64) * 80 + aRowOff;
        const uint32_t bBase = sbase + sbOff + (uint32_t)(73 + dt + nw * 32) * 80 + bRowOff;
        #pragma unroll
        for (int ks = 0; ks < 2; ks++) {
            uint32_t a[4][4];
            #pragma unroll
            for (int mt = 0; mt < 4; mt++)
                ldsm_x4(a[mt][0], a[mt][1], a[mt][2], a[mt][3],
                        aBase + mt * (16 * 80) + ks * 32);
            #pragma unroll
            for (int ntp = 0; ntp < 2; ntp++) {
                uint32_t b0, b1, b2, b3;
                ldsm_x4(b0, b1, b2, b3, bBase + ntp * (16 * 80) + ks * 32);
                #pragma unroll
                for (int mt = 0; mt < 4; mt++) {
                    mma16816(acc[mt][2 * ntp],     a[mt][0], a[mt][1], a[mt][2], a[mt][3], b0, b1);
                    mma16816(acc[mt][2 * ntp + 1], a[mt][0], a[mt][1], a[mt][2], a[mt][3], b2, b3);
                }
            }
        }

        // ---- stores of prefetched step s+1 ----
        if (doA) {
            uint32_t* dA = smem_u + ((sn & 1) ? SA1 : SA0);
            *(uint4*)&dA[oA * SROW + gA * 8]     = av0;
            *(uint4*)&dA[oA * SROW + gA * 8 + 4] = av1;
        }
        if (doB) {
            uint32_t* dB = smem_u + ((jB & 1) ? SB1 : SB0);
            *(uint4*)&dB[rB * SROW + gB * 8]     = bv0;
            *(uint4*)&dB[rB * SROW + gB * 8 + 4] = bv1;
        }
        __syncthreads();
    }

    // ---- epilogue: SMEM transpose, scale by g, float4 stores ----
    const int g = lane >> 2, t4 = lane & 3;
    float* eb = (float*)smem_u;   // 64 x 132
    #pragma unroll 1
    for (int r = 0; r < 2; r++) {
        __syncthreads();
        if (mw == r) {
            #pragma unroll
            for (int mt = 0; mt < 4; mt++)
                #pragma unroll
                for (int nt = 0; nt < 4; nt++) {
                    int row = mt * 16 + g;
                    int col = nw * 32 + nt * 8 + 2 * t4;
                    eb[row * 132 + col]           = acc[mt][nt][0];
                    eb[row * 132 + col + 1]       = acc[mt][nt][1];
                    eb[(row + 8) * 132 + col]     = acc[mt][nt][2];
                    eb[(row + 8) * 132 + col + 1] = acc[mt][nt][3];
                }
        }
        __syncthreads();
        for (int i = tid; i < 64 * 32; i += 256) {
            int ol = i >> 5, q4 = i & 31;
            int q = q0 + q4 * 4;
            int qr = q / WP, qc = q - qr * WP;
            if (qc < 64) {
                float4 v = *(float4*)&eb[ol * 132 + q4 * 4];
                int o = o0 + r * 64 + ol;
                float gv = d_g[b * OO + o];
                v.x *= gv; v.y *= gv; v.z *= gv; v.w *= gv;
                *(float4*)&out[(((size_t)b * OO + o) * 64 + qr - 1) * 64 + qc] = v;
            }
        }
    }
}

// ---------------- launch ----------------
extern "C" void kernel_launch(void* const* d_in, const int* in_sizes, int n_in,
                              void* d_out, int out_size) {
    const float *x = nullptr, *w = nullptr, *bw = nullptr, *mw = nullptr, *mb = nullptr;
    for (int i = 0; i < n_in; i++) {
        switch (in_sizes[i]) {
            case BB * CC * HH * WW: x  = (const float*)d_in[i]; break;
            case BB * 512:          w  = (const float*)d_in[i]; break;
            case OO * CC * 9:       bw = (const float*)d_in[i]; break;
            case OO * CC:           mw = (const float*)d_in[i]; break;
            case CC:                mb = (const float*)d_in[i]; break;
        }
    }
    float* out = (float*)d_out;

    cudaFuncSetAttribute(conv_mma_kernel, cudaFuncAttributeMaxDynamicSharedMemorySize, SMEM_DYN);

    s_kernel<<<(BB * CC * 32 + 255) / 256, 256>>>(w, mw, mb);
    w2_kernel<<<(OO * CC + 255) / 256, 256>>>(bw);
    g_kernel<<<(BB * OO * 32 + 255) / 256, 256>>>();
    xspad_kernel<<<dim3(32, 64, 8), 256>>>(x);
    padzero_kernel<<<(BB * 656 * 64 + 255) / 256, 256>>>();
    wpack_kernel<<<(int)(((size_t)9 * 16 * 512 * 16 + 255) / 256), 256>>>(bw);

    conv_mma_kernel<<<dim3(NQT, 4, BB), 256, SMEM_DYN>>>(out);
}

// round 8
// speedup vs baseline: 6.8069x; 1.0729x over previous
#include <cuda_runtime.h>
#include <cuda_fp16.h>
#include <cstdint>

// ---------------- problem constants ----------------
#define BB 8
#define CC 512
#define OO 512
#define HH 64
#define WW 64
#define MOD_SCALE_F 0.04419417382415922f   // 1/sqrt(512)

// padded flat grid: width 72, height 66
#define WP 72
#define QTOT (WP * 66)        // 4752
#define NQT 36                // q tiles of 128 covering [72, 4680)
#define ROWSB 274             // 128 + 2*73 halo rows
#define NWIN 48               // 16 c-chunks * 3 tap-groups

// SMEM word (b32) offsets, row stride 20 b32 (80 B, bank-coprime)
#define SROW 20
#define SA0 0
#define SA1 7680                       // 3*128*20
#define SB0 15360
#define SB1 (SB0 + ROWSB * SROW)       // 20840
#define SMEM_DYN ((SB1 + ROWSB * SROW) * 4)   // 105280 B

// ---------------- device scratch ----------------
__device__ float    d_s[BB * CC];
__device__ float    d_W2[OO * CC];
__device__ float    d_g[BB * OO];
__device__ __half   d_xsph[(size_t)BB * QTOT * CC];        // padded NHWC fp16
__device__ uint32_t d_Wp2u[(size_t)9 * 16 * 512 * 16];     // [t][j][o][c-pair] half2

__device__ __forceinline__ void mma16816(float* d, uint32_t a0, uint32_t a1,
                                         uint32_t a2, uint32_t a3,
                                         uint32_t b0, uint32_t b1) {
    asm volatile(
        "mma.sync.aligned.m16n8k16.row.col.f32.f16.f16.f32 "
        "{%0,%1,%2,%3}, {%4,%5,%6,%7}, {%8,%9}, {%0,%1,%2,%3};"
        : "+f"(d[0]), "+f"(d[1]), "+f"(d[2]), "+f"(d[3])
        : "r"(a0), "r"(a1), "r"(a2), "r"(a3), "r"(b0), "r"(b1));
}

__device__ __forceinline__ void ldsm_x4(uint32_t& r0, uint32_t& r1,
                                        uint32_t& r2, uint32_t& r3, uint32_t addr) {
    asm volatile("ldmatrix.sync.aligned.m8n8.x4.shared.b16 {%0,%1,%2,%3}, [%4];"
                 : "=r"(r0), "=r"(r1), "=r"(r2), "=r"(r3) : "r"(addr));
}

__device__ __forceinline__ uint32_t smem_u32(const void* p) {
    uint32_t a;
    asm("{ .reg .u64 t; cvta.to.shared.u64 t, %1; cvt.u32.u64 %0, t; }" : "=r"(a) : "l"(p));
    return a;
}

// 16B async copy with zero-fill predicate (src_size = 16 or 0)
__device__ __forceinline__ void cp16(uint32_t dst, const void* src, uint32_t sz) {
    asm volatile("cp.async.cg.shared.global [%0], [%1], 16, %2;"
                 :: "r"(dst), "l"(src), "r"(sz) : "memory");
}
#define CP_COMMIT() asm volatile("cp.async.commit_group;" ::: "memory")
#define CP_WAIT0()  asm volatile("cp.async.wait_group 0;" ::: "memory")

// ---------------- stage 1: s[b,c] ----------------
__global__ void s_kernel(const float* __restrict__ w, const float* __restrict__ mw,
                         const float* __restrict__ mb) {
    int gid = blockIdx.x * blockDim.x + threadIdx.x;
    int wid = gid >> 5, lane = gid & 31;
    if (wid >= BB * CC) return;
    int b = wid >> 9, c = wid & 511;
    const float* wr = w + b * 512;
    const float* mr = mw + c * 512;
    float acc = 0.f;
    #pragma unroll 4
    for (int d = lane; d < 512; d += 32) acc = fmaf(wr[d], mr[d], acc);
    #pragma unroll
    for (int o = 16; o; o >>= 1) acc += __shfl_xor_sync(0xffffffffu, acc, o);
    if (lane == 0) d_s[wid] = acc * MOD_SCALE_F + mb[c] + 1.0f;
}

// ---------------- stage 2: W2[o,c] ----------------
__global__ void w2_kernel(const float* __restrict__ bw) {
    int i = blockIdx.x * blockDim.x + threadIdx.x;
    if (i >= OO * CC) return;
    const float* p = bw + (size_t)i * 9;
    float a = 0.f;
    #pragma unroll
    for (int k = 0; k < 9; k++) { float v = p[k]; a = fmaf(v, v, a); }
    d_W2[i] = a;
}

// ---------------- stage 3: g[b,o] ----------------
__global__ void g_kernel() {
    int gid = blockIdx.x * blockDim.x + threadIdx.x;
    int wid = gid >> 5, lane = gid & 31;
    if (wid >= BB * OO) return;
    int b = wid >> 9, o = wid & 511;
    const float* sr = d_s + b * 512;
    const float* w2 = d_W2 + o * 512;
    float acc = 0.f;
    #pragma unroll 4
    for (int c = lane; c < 512; c += 32) { float sv = sr[c]; acc = fmaf(sv * sv, w2[c], acc); }
    #pragma unroll
    for (int o2 = 16; o2; o2 >>= 1) acc += __shfl_xor_sync(0xffffffffu, acc, o2);
    if (lane == 0) d_g[wid] = rsqrtf(acc);
}

// ---------------- stage 4a: modulated NCHW -> padded NHWC fp16 ----------------
__global__ void xspad_kernel(const float* __restrict__ x) {
    __shared__ float t[32][33];
    int tid = threadIdx.x;
    int b = blockIdx.z, h = blockIdx.y;
    int wt = blockIdx.x & 1, ct = blockIdx.x >> 1;
    int c0 = ct * 32, w0 = wt * 32;
    int a = tid & 31, bb2 = tid >> 5;
    #pragma unroll
    for (int i = 0; i < 4; i++) {
        int c = bb2 + i * 8;
        t[c][a] = x[(((size_t)b * CC + c0 + c) * HH + h) * WW + w0 + a] * d_s[b * CC + c0 + c];
    }
    __syncthreads();
    #pragma unroll
    for (int i = 0; i < 4; i++) {
        int w = bb2 + i * 8;
        d_xsph[((size_t)b * QTOT + (h + 1) * WP + w0 + w) * CC + c0 + a] =
            __float2half_rn(t[a][w]);
    }
}

// ---------------- stage 4b: zero pad cells ----------------
__global__ void padzero_kernel() {
    int i = blockIdx.x * blockDim.x + threadIdx.x;   // BB*656*64 uint4 (8 halves each)
    if (i >= BB * 656 * 64) return;
    int b = i / (656 * 64);
    int rem = i - b * (656 * 64);
    int p = rem >> 6, f = rem & 63;
    int q;
    if (p < 72) q = p;
    else if (p < 144) q = 4680 + (p - 72);
    else { int p2 = p - 144; q = (1 + (p2 >> 3)) * WP + 64 + (p2 & 7); }
    ((uint4*)d_xsph)[((size_t)b * QTOT + q) * 64 + f] = make_uint4(0u, 0u, 0u, 0u);
}

// ---------------- stage 5: pack weights as half2 pairs ----------------
// d_Wp2u[((t*16+j)*512+o)*16 + w] = half2(base[o][j*32+2w][t], base[o][j*32+2w+1][t])
__global__ void wpack_kernel(const float* __restrict__ bw) {
    size_t i = (size_t)blockIdx.x * 256 + threadIdx.x;
    if (i >= (size_t)9 * 16 * 512 * 16) return;
    int w = (int)(i & 15);
    int o = (int)((i >> 4) & 511);
    int j = (int)((i >> 13) & 15);
    int t = (int)(i >> 17);
    float v0 = bw[((size_t)o * 512 + j * 32 + 2 * w) * 9 + t];
    float v1 = bw[((size_t)o * 512 + j * 32 + 2 * w + 1) * 9 + t];
    __half2 h = __floats2half2_rn(v0, v1);
    d_Wp2u[i] = *(uint32_t*)&h;
}

// ---------------- stage 6: fp16 mma.sync + ldmatrix + cp.async conv ----------
__global__ __launch_bounds__(256, 2) void conv_mma_kernel(float* __restrict__ out) {
    extern __shared__ uint32_t smem_u[];
    const uint32_t sbase = smem_u32(smem_u);
    const int tid = threadIdx.x;
    const int wid = tid >> 5, lane = tid & 31;
    const int mw = wid & 1, nw = wid >> 1;     // o-warp (2), q-warp (4)
    const int tile = blockIdx.x, og = blockIdx.y, b = blockIdx.z;
    const int q0 = 72 + 128 * tile;
    const int qb = q0 - 73;
    const int o0 = og * 128;

    const int DT[9] = {-73, -72, -71, -1, 0, 1, 71, 72, 73};

    // per-lane ldmatrix address components (bytes), identical to R6
    const int aRowOff = (lane & 15) * 80 + (lane >> 4) * 16;
    const int bRowOff = ((lane & 7) + ((lane & 16) >> 1)) * 80 + ((lane & 8) << 1);

    float acc[4][4][4];
    #pragma unroll
    for (int mt = 0; mt < 4; mt++)
        #pragma unroll
        for (int nt = 0; nt < 4; nt++)
            #pragma unroll
            for (int r = 0; r < 4; r++) acc[mt][nt][r] = 0.f;

    const char* xBb = (const char*)(d_xsph + (size_t)b * QTOT * CC);   // bytes
    const char* wBb = (const char*)d_Wp2u;

    // ---- A window prefetch: 1536 16B units = (tap<3, row<128, seg<4) ----
    auto stageA = [&](int u, int jn, int tg3) {   // window u, chunk jn, tap-group tg3
        const uint32_t dstBase = sbase + ((u & 1) ? SA1 : SA0) * 4;
        #pragma unroll
        for (int p = 0; p < 6; p++) {
            int idx = p * 256 + tid;
            int seg = idx & 3, row = (idx >> 2) & 127, t = idx >> 9;
            int tap = tg3 * 3 + t;
            const void* src = wBb + (((size_t)(tap * 16 + jn) * 512 + o0 + row) << 6) + seg * 16;
            cp16(dstBase + (uint32_t)(t * 2560 + row * SROW + seg * 4) * 4, src, 16);
        }
    };
    // ---- B partial stage: units [lo, lo+366) of chunk jB's 1096 units ----
    auto stageBpart = [&](int jB, int lo) {
        const uint32_t dstBase = sbase + ((jB & 1) ? SB1 : SB0) * 4;
        #pragma unroll
        for (int k = 0; k < 2; k++) {
            int rel = k * 256 + tid;
            if (rel < 366) {
                int g = lo + rel;
                if (g < 1096) {
                    int r = g >> 2, seg = g & 3;
                    int gq = qb + r;
                    uint32_t ok = (gq >= 0 && gq < QTOT) ? 16u : 0u;
                    int gqc = ok ? gq : 0;
                    const void* src = xBb + ((size_t)gqc * 1024) + jB * 64 + seg * 16;
                    cp16(dstBase + (uint32_t)(r * SROW + seg * 4) * 4, src, ok);
                }
            }
        }
    };

    // ---- prologue: A window 0 (chunk 0, taps 0-2) + B chunk 0 ----
    stageA(0, 0, 0);
    {
        const uint32_t dstBase = sbase + SB0 * 4;
        for (int it = 0; it < 5; it++) {
            int g = it * 256 + tid;
            if (g < 1096) {
                int r = g >> 2, seg = g & 3;
                int gq = qb + r;
                uint32_t ok = (gq >= 0 && gq < QTOT) ? 16u : 0u;
                int gqc = ok ? gq : 0;
                const void* src = xBb + ((size_t)gqc * 1024) + seg * 16;
                cp16(dstBase + (uint32_t)(r * SROW + seg * 4) * 4, src, ok);
            }
        }
    }
    CP_COMMIT();
    CP_WAIT0();
    __syncthreads();

    // ---- main loop: 48 windows ----
    int j = 0, tg = 0;
    for (int u = 0; u < NWIN; u++) {
        // issue next-window A + next-chunk B slice
        const int un = u + 1;
        if (un < NWIN) {
            int jn = (tg == 2) ? j + 1 : j;
            int tgn = (tg == 2) ? 0 : tg + 1;
            stageA(un, jn, tgn);
        }
        if (j + 1 < 16) stageBpart(j + 1, tg * 366);
        CP_COMMIT();

        // compute: 3 taps from A[u&1], B[j&1]
        const uint32_t aWinBase = sbase + ((u & 1) ? SA1 : SA0) * 4 +
                                  (uint32_t)(mw * 64) * 80 + aRowOff;
        const uint32_t bChBase = sbase + ((j & 1) ? SB1 : SB0) * 4 + bRowOff;
        #pragma unroll
        for (int t = 0; t < 3; t++) {
            const int dt = DT[tg * 3 + t];
            const uint32_t aBase = aWinBase + (uint32_t)t * (2560 * 4);
            const uint32_t bBase = bChBase + (uint32_t)(73 + dt + nw * 32) * 80;
            #pragma unroll
            for (int ks = 0; ks < 2; ks++) {
                uint32_t a[4][4];
                #pragma unroll
                for (int mt = 0; mt < 4; mt++)
                    ldsm_x4(a[mt][0], a[mt][1], a[mt][2], a[mt][3],
                            aBase + mt * (16 * 80) + ks * 32);
                #pragma unroll
                for (int ntp = 0; ntp < 2; ntp++) {
                    uint32_t b0, b1, b2, b3;
                    ldsm_x4(b0, b1, b2, b3, bBase + ntp * (16 * 80) + ks * 32);
                    #pragma unroll
                    for (int mt = 0; mt < 4; mt++) {
                        mma16816(acc[mt][2 * ntp],     a[mt][0], a[mt][1], a[mt][2], a[mt][3], b0, b1);
                        mma16816(acc[mt][2 * ntp + 1], a[mt][0], a[mt][1], a[mt][2], a[mt][3], b2, b3);
                    }
                }
            }
        }

        CP_WAIT0();
        __syncthreads();

        if (tg == 2) { tg = 0; j++; } else tg++;
    }

    // ---- epilogue: SMEM transpose, scale by g, float4 stores ----
    const int g = lane >> 2, t4 = lane & 3;
    float* eb = (float*)smem_u;   // 64 x 132
    #pragma unroll 1
    for (int r = 0; r < 2; r++) {
        __syncthreads();
        if (mw == r) {
            #pragma unroll
            for (int mt = 0; mt < 4; mt++)
                #pragma unroll
                for (int nt = 0; nt < 4; nt++) {
                    int row = mt * 16 + g;
                    int col = nw * 32 + nt * 8 + 2 * t4;
                    eb[row * 132 + col]           = acc[mt][nt][0];
                    eb[row * 132 + col + 1]       = acc[mt][nt][1];
                    eb[(row + 8) * 132 + col]     = acc[mt][nt][2];
                    eb[(row + 8) * 132 + col + 1] = acc[mt][nt][3];
                }
        }
        __syncthreads();
        for (int i = tid; i < 64 * 32; i += 256) {
            int ol = i >> 5, q4 = i & 31;
            int q = q0 + q4 * 4;
            int qr = q / WP, qc = q - qr * WP;
            if (qc < 64) {
                float4 v = *(float4*)&eb[ol * 132 + q4 * 4];
                int o = o0 + r * 64 + ol;
                float gv = d_g[b * OO + o];
                v.x *= gv; v.y *= gv; v.z *= gv; v.w *= gv;
                *(float4*)&out[(((size_t)b * OO + o) * 64 + qr - 1) * 64 + qc] = v;
            }
        }
    }
}

// ---------------- launch ----------------
extern "C" void kernel_launch(void* const* d_in, const int* in_sizes, int n_in,
                              void* d_out, int out_size) {
    const float *x = nullptr, *w = nullptr, *bw = nullptr, *mw = nullptr, *mb = nullptr;
    for (int i = 0; i < n_in; i++) {
        switch (in_sizes[i]) {
            case BB * CC * HH * WW: x  = (const float*)d_in[i]; break;
            case BB * 512:          w  = (const float*)d_in[i]; break;
            case OO * CC * 9:       bw = (const float*)d_in[i]; break;
            case OO * CC:           mw = (const float*)d_in[i]; break;
            case CC:                mb = (const float*)d_in[i]; break;
        }
    }
    float* out = (float*)d_out;

    cudaFuncSetAttribute(conv_mma_kernel, cudaFuncAttributeMaxDynamicSharedMemorySize, SMEM_DYN);

    s_kernel<<<(BB * CC * 32 + 255) / 256, 256>>>(w, mw, mb);
    w2_kernel<<<(OO * CC + 255) / 256, 256>>>(bw);
    g_kernel<<<(BB * OO * 32 + 255) / 256, 256>>>();
    xspad_kernel<<<dim3(32, 64, 8), 256>>>(x);
    padzero_kernel<<<(BB * 656 * 64 + 255) / 256, 256>>>();
    wpack_kernel<<<(int)(((size_t)9 * 16 * 512 * 16 + 255) / 256), 256>>>(bw);

    conv_mma_kernel<<<dim3(NQT, 4, BB), 256, SMEM_DYN>>>(out);
}